// round 6
// baseline (speedup 1.0000x reference)
#include <cuda_runtime.h>
#include <cuda_bf16.h>
#include <math.h>

#define NMAX 50000
#define EMAX 800000
#define GMAX 500
#define HID  64

// ---------------- device scratch (static, no runtime allocation) ----------
__device__ int   g_is64;             // 1 if index tensors are int64, 0 if int32
__device__ int   g_deg[NMAX];        // in-degree + 1 (self loop)
__device__ int   g_fill[NMAX];       // fill cursors for CSR build
__device__ float g_dis[NMAX];        // rsqrt(deg)
__device__ int   g_rowptr[NMAX + 1]; // CSR row offsets (edges only)
__device__ int   g_col[EMAX];        // CSR column (src node) per edge
__device__ float g_bufA[NMAX * HID];
__device__ float g_bufB[NMAX * HID];

// Branch on detected dtype. g_is64 is set before any consumer runs.
__device__ __forceinline__ int load_idx(const void* p, long long i) {
    if (g_is64) return (int)((const long long*)p)[i];
    return ((const int*)p)[i];
}

// ---------------- detect dtype + init counters (fused) ---------------------
__global__ void detect_init_kernel(const int* __restrict__ ei32, int n) {
    int i = blockIdx.x * blockDim.x + threadIdx.x;
    if (i < n) { g_deg[i] = 1; g_fill[i] = 0; }

    if (blockIdx.x == 0) {
        __shared__ int acc[256];
        int t = threadIdx.x;
        int v = 0;
        for (int k = t; k < 2048; k += 256) v |= ei32[2 * k + 1];
        acc[t] = v;
        __syncthreads();
        for (int off = 128; off > 0; off >>= 1) {
            if (t < off) acc[t] |= acc[t + off];
            __syncthreads();
        }
        if (t == 0) g_is64 = (acc[0] == 0) ? 1 : 0;
    }
}

__global__ void deg_kernel(const void* __restrict__ ei, int e) {
    int i = blockIdx.x * blockDim.x + threadIdx.x;
    if (i < e) {
        int d = load_idx(ei, (long long)e + i);  // dst row of edge_index
        atomicAdd(&g_deg[d], 1);
    }
}

// Single-block exclusive prefix sum over (deg[i]-1) -> rowptr; also dis[].
__global__ void scan_kernel(int n, int e_total) {
    __shared__ int sh[1024];
    int t = threadIdx.x;
    int ch = (n + 1023) / 1024;
    int beg = t * ch;
    int end = min(beg + ch, n);
    int s = 0;
    for (int i = beg; i < end; ++i) {
        int dg = g_deg[i];
        s += dg - 1;
        g_dis[i] = rsqrtf((float)dg);
    }
    sh[t] = s;
    __syncthreads();
    for (int off = 1; off < 1024; off <<= 1) {
        int v = sh[t];
        int u = (t >= off) ? sh[t - off] : 0;
        __syncthreads();
        sh[t] = v + u;
        __syncthreads();
    }
    int excl = (t == 0) ? 0 : sh[t - 1];
    for (int i = beg; i < end; ++i) {
        g_rowptr[i] = excl;
        excl += g_deg[i] - 1;
    }
    if (t == 1023) g_rowptr[n] = e_total;
}

// CSR fill: column indices only (one scattered 4B write per edge).
__global__ void fill_kernel(const void* __restrict__ ei, int e) {
    int i = blockIdx.x * blockDim.x + threadIdx.x;
    if (i >= e) return;
    int s = load_idx(ei, i);
    int d = load_idx(ei, (long long)e + i);
    int pos = g_rowptr[d] + atomicAdd(&g_fill[d], 1);
    g_col[pos] = s;
}

// ---------------- u0 = dis[node] * x -----------------------------------------
__global__ void prescale_kernel(const float* __restrict__ x,
                                float* __restrict__ u, int n) {
    int i = blockIdx.x * blockDim.x + threadIdx.x;  // one float2 per thread
    if (i >= n * 32) return;
    int node = i >> 5;
    float d = g_dis[node];
    float2 v = reinterpret_cast<const float2*>(x)[i];
    v.x *= d; v.y *= d;
    reinterpret_cast<float2*>(u)[i] = v;
}

// ---------------- fused GCN layer: gather + GEMV + bias + relu -------------
// Input u = dis.*h_prev (pre-scaled). Per node d:
//   g = u[d] + sum_{e->d} u[src_e]          (weight-free gather)
//   h = relu(dis[d] * (g @ W) + b)
//   out = SCALE_OUT ? dis[d]*h : h
// One warp per node (looped, persistent-style grid). W staged in smem.
template <int SCALE_OUT>
__global__ void fused_layer_kernel(const float* __restrict__ u,
                                   const float* __restrict__ W,
                                   const float* __restrict__ bias,
                                   float* __restrict__ out, int n) {
    __shared__ float Ws[64 * 64];
    int tid = threadIdx.x;  // 512
#pragma unroll
    for (int i = 0; i < 8; ++i) Ws[tid + 512 * i] = W[tid + 512 * i];
    __syncthreads();

    int lane = tid & 31;
    int warp_g = (blockIdx.x * blockDim.x + tid) >> 5;
    int nwarps = (gridDim.x * blockDim.x) >> 5;

    float2 b = *reinterpret_cast<const float2*>(bias + lane * 2);

    for (int node = warp_g; node < n; node += nwarps) {
        // gather: acc holds components {2*lane, 2*lane+1} of g
        float2 acc = *reinterpret_cast<const float2*>(u + node * 64 + lane * 2);
        int beg = g_rowptr[node];
        int end = g_rowptr[node + 1];
        for (int e = beg; e < end; ++e) {
            int s = g_col[e];
            float2 v = *reinterpret_cast<const float2*>(u + s * 64 + lane * 2);
            acc.x += v.x;
            acc.y += v.y;
        }

        // GEMV: y[j] = sum_k g[k] * W[k][j], lane owns j = 2*lane, 2*lane+1
        float yx = 0.f, yy = 0.f;
#pragma unroll
        for (int kk = 0; kk < 32; ++kk) {
            float ax = __shfl_sync(0xffffffffu, acc.x, kk);
            float ay = __shfl_sync(0xffffffffu, acc.y, kk);
            float2 w0 = *reinterpret_cast<const float2*>(Ws + (2 * kk) * 64 + lane * 2);
            float2 w1 = *reinterpret_cast<const float2*>(Ws + (2 * kk + 1) * 64 + lane * 2);
            yx += ax * w0.x;  yy += ax * w0.y;
            yx += ay * w1.x;  yy += ay * w1.y;
        }

        float d = g_dis[node];
        float hx = fmaxf(d * yx + b.x, 0.f);
        float hy = fmaxf(d * yy + b.y, 0.f);
        if (SCALE_OUT) { hx *= d; hy *= d; }
        *reinterpret_cast<float2*>(out + node * 64 + lane * 2) =
            make_float2(hx, hy);
    }
}

// ---------------- mean pool + MLP + log_softmax (block per graph) ---------
__device__ __forceinline__ int lower_bound_batch(const void* batch, int n, int key) {
    int lo = 0, hi = n;
    while (lo < hi) {
        int mid = (lo + hi) >> 1;
        if (load_idx(batch, mid) < key) lo = mid + 1;
        else hi = mid;
    }
    return lo;
}

__global__ void pool_mlp_kernel(const float* __restrict__ h,
                                const void* __restrict__ batch, int n,
                                const float* __restrict__ lin1W,
                                const float* __restrict__ lin1b,
                                const float* __restrict__ lin2W,
                                const float* __restrict__ lin2b,
                                float* __restrict__ out) {
    int g   = blockIdx.x;
    int tid = threadIdx.x;  // 64
    __shared__ float pooled[64];
    __shared__ float h1[64];
    __shared__ float logits[10];
    __shared__ float lse;
    __shared__ int   sbeg, send;

    if (tid == 0) sbeg = lower_bound_batch(batch, n, g);
    if (tid == 32) send = lower_bound_batch(batch, n, g + 1);
    __syncthreads();
    int beg = sbeg, end = send;

    float s = 0.f;
    for (int r = beg; r < end; ++r) s += h[r * 64 + tid];
    int cnt = end - beg;
    pooled[tid] = s / (float)max(cnt, 1);
    __syncthreads();

    float a = lin1b[tid];
#pragma unroll
    for (int k = 0; k < 64; ++k) a += pooled[k] * lin1W[k * 64 + tid];
    h1[tid] = fmaxf(a, 0.f);
    __syncthreads();

    if (tid < 10) {
        float l = lin2b[tid];
#pragma unroll
        for (int k = 0; k < 64; ++k) l += h1[k] * lin2W[k * 10 + tid];
        logits[tid] = l;
    }
    __syncthreads();

    if (tid == 0) {
        float m = logits[0];
        for (int j = 1; j < 10; ++j) m = fmaxf(m, logits[j]);
        float se = 0.f;
        for (int j = 0; j < 10; ++j) se += expf(logits[j] - m);
        lse = m + logf(se);
    }
    __syncthreads();

    if (tid < 10) out[g * 10 + tid] = logits[tid] - lse;
}

// ---------------- launch ---------------------------------------------------
extern "C" void kernel_launch(void* const* d_in, const int* in_sizes, int n_in,
                              void* d_out, int out_size) {
    const float* x     = (const float*)d_in[0];
    const void*  ei    = d_in[1];
    const void*  batch = d_in[2];
    const float* W1 = (const float*)d_in[3];
    const float* b1 = (const float*)d_in[4];
    const float* W2 = (const float*)d_in[5];
    const float* b2 = (const float*)d_in[6];
    const float* W3 = (const float*)d_in[7];
    const float* b3 = (const float*)d_in[8];
    const float* l1W = (const float*)d_in[9];
    const float* l1b = (const float*)d_in[10];
    const float* l2W = (const float*)d_in[11];
    const float* l2b = (const float*)d_in[12];
    float* out = (float*)d_out;

    const int n = in_sizes[0] / HID;
    const int e = in_sizes[1] / 2;
    const int G = out_size / 10;

    float* bufA = nullptr;
    float* bufB = nullptr;
    cudaGetSymbolAddress((void**)&bufA, g_bufA);
    cudaGetSymbolAddress((void**)&bufB, g_bufB);

    int tpb = 256;
    detect_init_kernel<<<(n + tpb - 1) / tpb, tpb>>>((const int*)ei, n);
    deg_kernel<<<(e + tpb - 1) / tpb, tpb>>>(ei, e);
    scan_kernel<<<1, 1024>>>(n, e);
    fill_kernel<<<(e + tpb - 1) / tpb, tpb>>>(ei, e);

    prescale_kernel<<<(n * 32 + tpb - 1) / tpb, tpb>>>(x, bufA, n);

    const int FB = 592;   // 4 blocks/SM, 512 threads each
    fused_layer_kernel<1><<<FB, 512>>>(bufA, W1, b1, bufB, n);
    fused_layer_kernel<1><<<FB, 512>>>(bufB, W2, b2, bufA, n);
    fused_layer_kernel<0><<<FB, 512>>>(bufA, W3, b3, bufB, n);

    pool_mlp_kernel<<<G, 64>>>(bufB, batch, n, l1W, l1b, l2W, l2b, out);
}

// round 7
// speedup vs baseline: 1.0603x; 1.0603x over previous
#include <cuda_runtime.h>
#include <cuda_bf16.h>
#include <math.h>

#define NMAX 50000
#define EMAX 800000
#define GMAX 500
#define HID  64

// ---------------- device scratch (static, no runtime allocation) ----------
__device__ int   g_is64;             // 1 if index tensors are int64, 0 if int32
__device__ int   g_deg[NMAX];        // in-degree + 1 (self loop)
__device__ int   g_fill[NMAX];       // fill cursors for CSR build
__device__ float g_dis[NMAX];        // rsqrt(deg)
__device__ int   g_rowptr[NMAX + 1]; // CSR row offsets (edges only)
__device__ int   g_col[EMAX];        // CSR column (src node) per edge
__device__ float g_bufA[NMAX * HID];
__device__ float g_bufB[NMAX * HID];

// Branch on detected dtype. g_is64 is set before any consumer runs.
__device__ __forceinline__ int load_idx(const void* p, long long i) {
    if (g_is64) return (int)((const long long*)p)[i];
    return ((const int*)p)[i];
}

// ---------------- detect dtype + init counters (fused) ---------------------
__global__ void detect_init_kernel(const int* __restrict__ ei32, int n) {
    int i = blockIdx.x * blockDim.x + threadIdx.x;
    if (i < n) { g_deg[i] = 1; g_fill[i] = 0; }

    if (blockIdx.x == 0) {
        __shared__ int acc[256];
        int t = threadIdx.x;
        int v = 0;
        for (int k = t; k < 2048; k += 256) v |= ei32[2 * k + 1];
        acc[t] = v;
        __syncthreads();
        for (int off = 128; off > 0; off >>= 1) {
            if (t < off) acc[t] |= acc[t + off];
            __syncthreads();
        }
        if (t == 0) g_is64 = (acc[0] == 0) ? 1 : 0;
    }
}

__global__ void deg_kernel(const void* __restrict__ ei, int e) {
    int i = blockIdx.x * blockDim.x + threadIdx.x;
    if (i < e) {
        int d = load_idx(ei, (long long)e + i);  // dst row of edge_index
        atomicAdd(&g_deg[d], 1);
    }
}

// Single-block exclusive prefix sum over (deg[i]-1) -> rowptr; also dis[].
__global__ void scan_kernel(int n, int e_total) {
    __shared__ int sh[1024];
    int t = threadIdx.x;
    int ch = (n + 1023) / 1024;
    int beg = t * ch;
    int end = min(beg + ch, n);
    int s = 0;
    for (int i = beg; i < end; ++i) {
        int dg = g_deg[i];
        s += dg - 1;
        g_dis[i] = rsqrtf((float)dg);
    }
    sh[t] = s;
    __syncthreads();
    for (int off = 1; off < 1024; off <<= 1) {
        int v = sh[t];
        int u = (t >= off) ? sh[t - off] : 0;
        __syncthreads();
        sh[t] = v + u;
        __syncthreads();
    }
    int excl = (t == 0) ? 0 : sh[t - 1];
    for (int i = beg; i < end; ++i) {
        g_rowptr[i] = excl;
        excl += g_deg[i] - 1;
    }
    if (t == 1023) g_rowptr[n] = e_total;
}

// CSR fill: column indices only (one scattered 4B write per edge).
__global__ void fill_kernel(const void* __restrict__ ei, int e) {
    int i = blockIdx.x * blockDim.x + threadIdx.x;
    if (i >= e) return;
    int s = load_idx(ei, i);
    int d = load_idx(ei, (long long)e + i);
    int pos = g_rowptr[d] + atomicAdd(&g_fill[d], 1);
    g_col[pos] = s;
}

// ---------------- dense 64x64 GEMM with dis-scaled epilogue ----------------
// out[row] = dis[row] * (in[row] @ W).
__global__ void gemm64_kernel(const float* __restrict__ in,
                              const float* __restrict__ W,
                              float* __restrict__ out, int n) {
    __shared__ float Ws[64 * 64];
    int tid = threadIdx.x;  // 256
#pragma unroll
    for (int i = 0; i < 16; ++i) Ws[tid + 256 * i] = W[tid + 256 * i];
    __syncthreads();

    int row  = blockIdx.x * 128 + (tid & 127);
    int half = tid >> 7;   // uniform per warp
    if (row >= n) return;

    float acc[32];
#pragma unroll
    for (int j = 0; j < 32; ++j) acc[j] = 0.f;

    const float4* xr = reinterpret_cast<const float4*>(in + row * 64);
    const float*  wb = Ws + half * 32;

#pragma unroll 2
    for (int k4 = 0; k4 < 16; ++k4) {
        float4 xv = xr[k4];
        float xk[4] = {xv.x, xv.y, xv.z, xv.w};
#pragma unroll
        for (int kk = 0; kk < 4; ++kk) {
            const float4* wrow =
                reinterpret_cast<const float4*>(wb + (k4 * 4 + kk) * 64);
#pragma unroll
            for (int j4 = 0; j4 < 8; ++j4) {
                float4 wv = wrow[j4];
                acc[j4 * 4 + 0] += xk[kk] * wv.x;
                acc[j4 * 4 + 1] += xk[kk] * wv.y;
                acc[j4 * 4 + 2] += xk[kk] * wv.z;
                acc[j4 * 4 + 3] += xk[kk] * wv.w;
            }
        }
    }

    float ds = g_dis[row];
    float4* o = reinterpret_cast<float4*>(out + row * 64 + half * 32);
#pragma unroll
    for (int j4 = 0; j4 < 8; ++j4)
        o[j4] = make_float4(ds * acc[j4 * 4], ds * acc[j4 * 4 + 1],
                            ds * acc[j4 * 4 + 2], ds * acc[j4 * 4 + 3]);
}

// ---------------- fused: agg_k (gather+bias+relu) + gemm_{k+1} -------------
// t holds dis.*(h@W) from the previous GEMM. Per 64-node tile:
//  phase1 (warp per node): g = relu(dis[d]*(t[d]+sum t[src]) + b)  -> smem
//  phase2 (gemm64-style):  out[d] = dis[d] * (g[d] @ Wnext)
// W reads in phase2 are warp-uniform (broadcast). g reads conflict-free via
// row pad 67 ((3r+k) mod 32 distinct over a warp's 32 rows).
__global__ void fused_layer_kernel(const float* __restrict__ t,
                                   const float* __restrict__ W,     // W_{k+1}
                                   const float* __restrict__ bias,  // b_k
                                   float* __restrict__ out, int n) {
    __shared__ float Ws[64 * 64];
    __shared__ float Gs[64][67];
    int tid  = threadIdx.x;  // 256
    int lane = tid & 31;
    int warp = tid >> 5;

#pragma unroll
    for (int i = 0; i < 16; ++i) Ws[tid + 256 * i] = W[tid + 256 * i];

    int tile0 = blockIdx.x * 64;
    float2 bv = *reinterpret_cast<const float2*>(bias + lane * 2);

    // phase 1: gather for 8 nodes per warp
#pragma unroll
    for (int r = warp; r < 64; r += 8) {
        int node = tile0 + r;
        if (node < n) {
            float2 acc = *reinterpret_cast<const float2*>(t + node * 64 + lane * 2);
            int beg = g_rowptr[node];
            int end = g_rowptr[node + 1];
            for (int e = beg; e < end; ++e) {
                int s = g_col[e];
                float2 v = *reinterpret_cast<const float2*>(t + s * 64 + lane * 2);
                acc.x += v.x;
                acc.y += v.y;
            }
            float d = g_dis[node];
            Gs[r][lane * 2]     = fmaxf(d * acc.x + bv.x, 0.f);
            Gs[r][lane * 2 + 1] = fmaxf(d * acc.y + bv.y, 0.f);
        }
    }
    __syncthreads();

    // phase 2: GEMV, 4 threads per row, 16 outputs each
    int row  = tid & 63;
    int q    = tid >> 6;   // 0..3, warp-uniform
    int node = tile0 + row;
    if (node >= n) return;

    float acc[16];
#pragma unroll
    for (int j = 0; j < 16; ++j) acc[j] = 0.f;

#pragma unroll 4
    for (int k = 0; k < 64; ++k) {
        float gk = Gs[row][k];
        const float4* wr = reinterpret_cast<const float4*>(Ws + k * 64 + q * 16);
#pragma unroll
        for (int j4 = 0; j4 < 4; ++j4) {
            float4 wv = wr[j4];
            acc[j4 * 4 + 0] += gk * wv.x;
            acc[j4 * 4 + 1] += gk * wv.y;
            acc[j4 * 4 + 2] += gk * wv.z;
            acc[j4 * 4 + 3] += gk * wv.w;
        }
    }

    float ds = g_dis[node];
    float4* o = reinterpret_cast<float4*>(out + node * 64 + q * 16);
#pragma unroll
    for (int j4 = 0; j4 < 4; ++j4)
        o[j4] = make_float4(ds * acc[j4 * 4], ds * acc[j4 * 4 + 1],
                            ds * acc[j4 * 4 + 2], ds * acc[j4 * 4 + 3]);
}

// ---------------- final aggregation (layer 3, no following GEMM) -----------
__global__ void agg_kernel(const float* __restrict__ t,
                           const float* __restrict__ bias,
                           float* __restrict__ out, int n) {
    int wid  = (blockIdx.x * blockDim.x + threadIdx.x) >> 5;
    int lane = threadIdx.x & 31;
    if (wid >= n) return;

    float2 acc = *reinterpret_cast<const float2*>(t + wid * 64 + lane * 2);
    int beg = g_rowptr[wid];
    int end = g_rowptr[wid + 1];
    for (int e = beg; e < end; ++e) {
        int s = g_col[e];
        float2 v = *reinterpret_cast<const float2*>(t + s * 64 + lane * 2);
        acc.x += v.x;
        acc.y += v.y;
    }

    float d = g_dis[wid];
    float2 b = *reinterpret_cast<const float2*>(bias + lane * 2);
    float2 r;
    r.x = fmaxf(d * acc.x + b.x, 0.f);
    r.y = fmaxf(d * acc.y + b.y, 0.f);
    *reinterpret_cast<float2*>(out + wid * 64 + lane * 2) = r;
}

// ---------------- mean pool + MLP + log_softmax (block per graph) ---------
__device__ __forceinline__ int lower_bound_batch(const void* batch, int n, int key) {
    int lo = 0, hi = n;
    while (lo < hi) {
        int mid = (lo + hi) >> 1;
        if (load_idx(batch, mid) < key) lo = mid + 1;
        else hi = mid;
    }
    return lo;
}

__global__ void pool_mlp_kernel(const float* __restrict__ h,
                                const void* __restrict__ batch, int n,
                                const float* __restrict__ lin1W,
                                const float* __restrict__ lin1b,
                                const float* __restrict__ lin2W,
                                const float* __restrict__ lin2b,
                                float* __restrict__ out) {
    int g   = blockIdx.x;
    int tid = threadIdx.x;  // 64
    __shared__ float pooled[64];
    __shared__ float h1[64];
    __shared__ float logits[10];
    __shared__ float lse;
    __shared__ int   sbeg, send;

    if (tid == 0) sbeg = lower_bound_batch(batch, n, g);
    if (tid == 32) send = lower_bound_batch(batch, n, g + 1);
    __syncthreads();
    int beg = sbeg, end = send;

    float s = 0.f;
    for (int r = beg; r < end; ++r) s += h[r * 64 + tid];
    int cnt = end - beg;
    pooled[tid] = s / (float)max(cnt, 1);
    __syncthreads();

    float a = lin1b[tid];
#pragma unroll
    for (int k = 0; k < 64; ++k) a += pooled[k] * lin1W[k * 64 + tid];
    h1[tid] = fmaxf(a, 0.f);
    __syncthreads();

    if (tid < 10) {
        float l = lin2b[tid];
#pragma unroll
        for (int k = 0; k < 64; ++k) l += h1[k] * lin2W[k * 10 + tid];
        logits[tid] = l;
    }
    __syncthreads();

    if (tid == 0) {
        float m = logits[0];
        for (int j = 1; j < 10; ++j) m = fmaxf(m, logits[j]);
        float se = 0.f;
        for (int j = 0; j < 10; ++j) se += expf(logits[j] - m);
        lse = m + logf(se);
    }
    __syncthreads();

    if (tid < 10) out[g * 10 + tid] = logits[tid] - lse;
}

// ---------------- launch ---------------------------------------------------
extern "C" void kernel_launch(void* const* d_in, const int* in_sizes, int n_in,
                              void* d_out, int out_size) {
    const float* x     = (const float*)d_in[0];
    const void*  ei    = d_in[1];
    const void*  batch = d_in[2];
    const float* W1 = (const float*)d_in[3];
    const float* b1 = (const float*)d_in[4];
    const float* W2 = (const float*)d_in[5];
    const float* b2 = (const float*)d_in[6];
    const float* W3 = (const float*)d_in[7];
    const float* b3 = (const float*)d_in[8];
    const float* l1W = (const float*)d_in[9];
    const float* l1b = (const float*)d_in[10];
    const float* l2W = (const float*)d_in[11];
    const float* l2b = (const float*)d_in[12];
    float* out = (float*)d_out;

    const int n = in_sizes[0] / HID;
    const int e = in_sizes[1] / 2;
    const int G = out_size / 10;

    float* bufA = nullptr;
    float* bufB = nullptr;
    cudaGetSymbolAddress((void**)&bufA, g_bufA);
    cudaGetSymbolAddress((void**)&bufB, g_bufB);

    // Side stream + events for overlapping fill with gemm1 (fork/join inside
    // graph capture). Created fresh per call; host-side resources only.
    cudaStream_t s2;
    cudaEvent_t evFork, evJoin;
    cudaStreamCreateWithFlags(&s2, cudaStreamNonBlocking);
    cudaEventCreateWithFlags(&evFork, cudaEventDisableTiming);
    cudaEventCreateWithFlags(&evJoin, cudaEventDisableTiming);

    int tpb = 256;
    detect_init_kernel<<<(n + tpb - 1) / tpb, tpb>>>((const int*)ei, n);
    deg_kernel<<<(e + tpb - 1) / tpb, tpb>>>(ei, e);
    scan_kernel<<<1, 1024>>>(n, e);

    // fork: fill (CSR columns) runs concurrently with gemm1
    cudaEventRecord(evFork, 0);
    cudaStreamWaitEvent(s2, evFork, 0);
    fill_kernel<<<(e + tpb - 1) / tpb, tpb, 0, s2>>>(ei, e);
    cudaEventRecord(evJoin, s2);

    gemm64_kernel<<<(n + 127) / 128, 256>>>(x, W1, bufB, n);  // t1

    cudaStreamWaitEvent(0, evJoin, 0);  // join: fused layers need CSR + t1

    int fused_blocks = (n + 63) / 64;
    fused_layer_kernel<<<fused_blocks, 256>>>(bufB, W2, b1, bufA, n);  // t2
    fused_layer_kernel<<<fused_blocks, 256>>>(bufA, W3, b2, bufB, n);  // t3

    int agg_blocks = (n * 32 + tpb - 1) / tpb;
    agg_kernel<<<agg_blocks, tpb>>>(bufB, b3, bufA, n);  // h3

    pool_mlp_kernel<<<G, 64>>>(bufA, batch, n, l1W, l1b, l2W, l2b, out);
}

// round 8
// speedup vs baseline: 1.1606x; 1.0946x over previous
#include <cuda_runtime.h>
#include <cuda_fp16.h>
#include <math.h>

#define NMAX 50000
#define EMAX 800000
#define GMAX 500
#define HID  64

// ---------------- device scratch (static, no runtime allocation) ----------
__device__ int     g_is64;             // 1 if index tensors are int64, 0 if int32
__device__ int     g_deg[NMAX];        // in-degree + 1 (self loop)
__device__ int     g_fill[NMAX];       // fill cursors for CSR build
__device__ float   g_dis[NMAX];        // rsqrt(deg)
__device__ int     g_rowptr[NMAX + 1]; // CSR row offsets (edges only)
__device__ int     g_col[EMAX];        // CSR column (src node) per edge
__device__ __half2 g_bufT[NMAX * 32];  // gathered operand, fp16 (dis-scaled h@W)
__device__ float   g_bufH[NMAX * HID]; // relu activations, fp32

// Branch on detected dtype. g_is64 is set before any consumer runs.
__device__ __forceinline__ int load_idx(const void* p, long long i) {
    if (g_is64) return (int)((const long long*)p)[i];
    return ((const int*)p)[i];
}

// ---------------- detect dtype + init counters (fused) ---------------------
__global__ void detect_init_kernel(const int* __restrict__ ei32, int n) {
    int i = blockIdx.x * blockDim.x + threadIdx.x;
    if (i < n) { g_deg[i] = 1; g_fill[i] = 0; }

    if (blockIdx.x == 0) {
        __shared__ int acc[256];
        int t = threadIdx.x;
        int v = 0;
        for (int k = t; k < 2048; k += 256) v |= ei32[2 * k + 1];
        acc[t] = v;
        __syncthreads();
        for (int off = 128; off > 0; off >>= 1) {
            if (t < off) acc[t] |= acc[t + off];
            __syncthreads();
        }
        if (t == 0) g_is64 = (acc[0] == 0) ? 1 : 0;
    }
}

__global__ void deg_kernel(const void* __restrict__ ei, int e) {
    int i = blockIdx.x * blockDim.x + threadIdx.x;
    if (i < e) {
        int d = load_idx(ei, (long long)e + i);  // dst row of edge_index
        atomicAdd(&g_deg[d], 1);
    }
}

// Single-block exclusive prefix sum over (deg[i]-1) -> rowptr; also dis[].
__global__ void scan_kernel(int n, int e_total) {
    __shared__ int sh[1024];
    int t = threadIdx.x;
    int ch = (n + 1023) / 1024;
    int beg = t * ch;
    int end = min(beg + ch, n);
    int s = 0;
    for (int i = beg; i < end; ++i) {
        int dg = g_deg[i];
        s += dg - 1;
        g_dis[i] = rsqrtf((float)dg);
    }
    sh[t] = s;
    __syncthreads();
    for (int off = 1; off < 1024; off <<= 1) {
        int v = sh[t];
        int u = (t >= off) ? sh[t - off] : 0;
        __syncthreads();
        sh[t] = v + u;
        __syncthreads();
    }
    int excl = (t == 0) ? 0 : sh[t - 1];
    for (int i = beg; i < end; ++i) {
        g_rowptr[i] = excl;
        excl += g_deg[i] - 1;
    }
    if (t == 1023) g_rowptr[n] = e_total;
}

// CSR fill: column indices only (one scattered 4B write per edge).
__global__ void fill_kernel(const void* __restrict__ ei, int e) {
    int i = blockIdx.x * blockDim.x + threadIdx.x;
    if (i >= e) return;
    int s = load_idx(ei, i);
    int d = load_idx(ei, (long long)e + i);
    int pos = g_rowptr[d] + atomicAdd(&g_fill[d], 1);
    g_col[pos] = s;
}

// ---------------- dense 64x64 GEMM, dis-scaled epilogue, fp16 output -------
// T[row] = half( dis[row] * (in[row] @ W) ).
__global__ void gemm64_kernel(const float* __restrict__ in,
                              const float* __restrict__ W,
                              __half2* __restrict__ outT, int n) {
    __shared__ float Ws[64 * 64];
    int tid = threadIdx.x;  // 256
#pragma unroll
    for (int i = 0; i < 16; ++i) Ws[tid + 256 * i] = W[tid + 256 * i];
    __syncthreads();

    int row  = blockIdx.x * 128 + (tid & 127);
    int half = tid >> 7;   // uniform per warp
    if (row >= n) return;

    float acc[32];
#pragma unroll
    for (int j = 0; j < 32; ++j) acc[j] = 0.f;

    const float4* xr = reinterpret_cast<const float4*>(in + row * 64);
    const float*  wb = Ws + half * 32;

#pragma unroll 2
    for (int k4 = 0; k4 < 16; ++k4) {
        float4 xv = xr[k4];
        float xk[4] = {xv.x, xv.y, xv.z, xv.w};
#pragma unroll
        for (int kk = 0; kk < 4; ++kk) {
            const float4* wrow =
                reinterpret_cast<const float4*>(wb + (k4 * 4 + kk) * 64);
#pragma unroll
            for (int j4 = 0; j4 < 8; ++j4) {
                float4 wv = wrow[j4];
                acc[j4 * 4 + 0] += xk[kk] * wv.x;
                acc[j4 * 4 + 1] += xk[kk] * wv.y;
                acc[j4 * 4 + 2] += xk[kk] * wv.z;
                acc[j4 * 4 + 3] += xk[kk] * wv.w;
            }
        }
    }

    float ds = g_dis[row];
    __half2 hh[16];
#pragma unroll
    for (int j2 = 0; j2 < 16; ++j2)
        hh[j2] = __floats2half2_rn(ds * acc[j2 * 2], ds * acc[j2 * 2 + 1]);

    // 16 half2 = 64 B -> 4 x 16B stores
    uint4* o = reinterpret_cast<uint4*>(outT + row * 32 + half * 16);
    const uint4* hsrc = reinterpret_cast<const uint4*>(hh);
#pragma unroll
    for (int j = 0; j < 4; ++j) o[j] = hsrc[j];
}

// ---------------- per-node aggregation + bias + relu (warp per node) ------
// Weight-free gather over fp16 rows (lane owns features 2*lane, 2*lane+1).
__global__ void agg_kernel(const __half2* __restrict__ t,
                           const float* __restrict__ bias,
                           float* __restrict__ outH, int n) {
    int wid  = (blockIdx.x * blockDim.x + threadIdx.x) >> 5;
    int lane = threadIdx.x & 31;
    if (wid >= n) return;

    float2 acc = __half22float2(t[wid * 32 + lane]);  // self-loop term
    int beg = g_rowptr[wid];
    int end = g_rowptr[wid + 1];
    for (int e = beg; e < end; ++e) {
        int s = g_col[e];
        float2 v = __half22float2(t[s * 32 + lane]);
        acc.x += v.x;
        acc.y += v.y;
    }

    float d = g_dis[wid];
    float2 b = *reinterpret_cast<const float2*>(bias + lane * 2);
    float2 r;
    r.x = fmaxf(d * acc.x + b.x, 0.f);
    r.y = fmaxf(d * acc.y + b.y, 0.f);
    *reinterpret_cast<float2*>(outH + wid * 64 + lane * 2) = r;
}

// ---------------- mean pool + MLP + log_softmax (block per graph) ---------
__device__ __forceinline__ int lower_bound_batch(const void* batch, int n, int key) {
    int lo = 0, hi = n;
    while (lo < hi) {
        int mid = (lo + hi) >> 1;
        if (load_idx(batch, mid) < key) lo = mid + 1;
        else hi = mid;
    }
    return lo;
}

__global__ void pool_mlp_kernel(const float* __restrict__ h,
                                const void* __restrict__ batch, int n,
                                const float* __restrict__ lin1W,
                                const float* __restrict__ lin1b,
                                const float* __restrict__ lin2W,
                                const float* __restrict__ lin2b,
                                float* __restrict__ out) {
    int g   = blockIdx.x;
    int tid = threadIdx.x;  // 64
    __shared__ float pooled[64];
    __shared__ float h1[64];
    __shared__ float logits[10];
    __shared__ float lse;
    __shared__ int   sbeg, send;

    if (tid == 0) sbeg = lower_bound_batch(batch, n, g);
    if (tid == 32) send = lower_bound_batch(batch, n, g + 1);
    __syncthreads();
    int beg = sbeg, end = send;

    float s = 0.f;
    for (int r = beg; r < end; ++r) s += h[r * 64 + tid];
    int cnt = end - beg;
    pooled[tid] = s / (float)max(cnt, 1);
    __syncthreads();

    float a = lin1b[tid];
#pragma unroll
    for (int k = 0; k < 64; ++k) a += pooled[k] * lin1W[k * 64 + tid];
    h1[tid] = fmaxf(a, 0.f);
    __syncthreads();

    if (tid < 10) {
        float l = lin2b[tid];
#pragma unroll
        for (int k = 0; k < 64; ++k) l += h1[k] * lin2W[k * 10 + tid];
        logits[tid] = l;
    }
    __syncthreads();

    if (tid == 0) {
        float m = logits[0];
        for (int j = 1; j < 10; ++j) m = fmaxf(m, logits[j]);
        float se = 0.f;
        for (int j = 0; j < 10; ++j) se += expf(logits[j] - m);
        lse = m + logf(se);
    }
    __syncthreads();

    if (tid < 10) out[g * 10 + tid] = logits[tid] - lse;
}

// ---------------- launch ---------------------------------------------------
extern "C" void kernel_launch(void* const* d_in, const int* in_sizes, int n_in,
                              void* d_out, int out_size) {
    const float* x     = (const float*)d_in[0];
    const void*  ei    = d_in[1];
    const void*  batch = d_in[2];
    const float* W1 = (const float*)d_in[3];
    const float* b1 = (const float*)d_in[4];
    const float* W2 = (const float*)d_in[5];
    const float* b2 = (const float*)d_in[6];
    const float* W3 = (const float*)d_in[7];
    const float* b3 = (const float*)d_in[8];
    const float* l1W = (const float*)d_in[9];
    const float* l1b = (const float*)d_in[10];
    const float* l2W = (const float*)d_in[11];
    const float* l2b = (const float*)d_in[12];
    float* out = (float*)d_out;

    const int n = in_sizes[0] / HID;
    const int e = in_sizes[1] / 2;
    const int G = out_size / 10;

    __half2* bufT = nullptr;
    float*   bufH = nullptr;
    cudaGetSymbolAddress((void**)&bufT, g_bufT);
    cudaGetSymbolAddress((void**)&bufH, g_bufH);

    // Side stream + events for overlapping fill with gemm1 (fork/join inside
    // graph capture).
    cudaStream_t s2;
    cudaEvent_t evFork, evJoin;
    cudaStreamCreateWithFlags(&s2, cudaStreamNonBlocking);
    cudaEventCreateWithFlags(&evFork, cudaEventDisableTiming);
    cudaEventCreateWithFlags(&evJoin, cudaEventDisableTiming);

    int tpb = 256;
    detect_init_kernel<<<(n + tpb - 1) / tpb, tpb>>>((const int*)ei, n);
    deg_kernel<<<(e + tpb - 1) / tpb, tpb>>>(ei, e);
    scan_kernel<<<1, 1024>>>(n, e);

    // fork: fill (CSR columns) concurrently with gemm1
    cudaEventRecord(evFork, 0);
    cudaStreamWaitEvent(s2, evFork, 0);
    fill_kernel<<<(e + tpb - 1) / tpb, tpb, 0, s2>>>(ei, e);
    cudaEventRecord(evJoin, s2);

    int gemm_blocks = (n + 127) / 128;
    int agg_blocks  = (n * 32 + tpb - 1) / tpb;

    gemm64_kernel<<<gemm_blocks, 256>>>(x, W1, bufT, n);   // T1

    cudaStreamWaitEvent(0, evJoin, 0);  // aggs need the CSR columns

    agg_kernel<<<agg_blocks, tpb>>>(bufT, b1, bufH, n);    // H1
    gemm64_kernel<<<gemm_blocks, 256>>>(bufH, W2, bufT, n); // T2
    agg_kernel<<<agg_blocks, tpb>>>(bufT, b2, bufH, n);    // H2
    gemm64_kernel<<<gemm_blocks, 256>>>(bufH, W3, bufT, n); // T3
    agg_kernel<<<agg_blocks, tpb>>>(bufT, b3, bufH, n);    // H3

    pool_mlp_kernel<<<G, 64>>>(bufH, batch, n, l1W, l1b, l2W, l2b, out);
}

// round 9
// speedup vs baseline: 1.1912x; 1.0264x over previous
#include <cuda_runtime.h>
#include <cuda_fp16.h>
#include <math.h>

#define NMAX 50000
#define EMAX 800000
#define GMAX 500
#define HID  64

// ---------------- device scratch (static, no runtime allocation) ----------
__device__ int     g_is64;             // 1 if index tensors are int64, 0 if int32
__device__ int     g_deg[NMAX];        // in-degree + 1 (self loop)
__device__ int     g_fill[NMAX];       // fill cursors for CSR build
__device__ float   g_dis[NMAX];        // rsqrt(deg)
__device__ int     g_rowptr[NMAX + 1]; // CSR row offsets (edges only)
__device__ int     g_col[EMAX];        // CSR column (src node) per edge
__device__ __half2 g_bufT[NMAX * 32];  // gathered operand, fp16 (dis-scaled h@W)
__device__ float   g_bufH[NMAX * HID]; // relu activations, fp32

// Branch on detected dtype. g_is64 is set before any consumer runs.
__device__ __forceinline__ int load_idx(const void* p, long long i) {
    if (g_is64) return (int)((const long long*)p)[i];
    return ((const int*)p)[i];
}

// ---------------- detect dtype + init counters (fused) ---------------------
__global__ void detect_init_kernel(const int* __restrict__ ei32, int n) {
    int i = blockIdx.x * blockDim.x + threadIdx.x;
    if (i < n) { g_deg[i] = 1; g_fill[i] = 0; }

    if (blockIdx.x == 0) {
        __shared__ int acc[256];
        int t = threadIdx.x;
        int v = 0;
        for (int k = t; k < 2048; k += 256) v |= ei32[2 * k + 1];
        acc[t] = v;
        __syncthreads();
        for (int off = 128; off > 0; off >>= 1) {
            if (t < off) acc[t] |= acc[t + off];
            __syncthreads();
        }
        if (t == 0) g_is64 = (acc[0] == 0) ? 1 : 0;
    }
}

__global__ void deg_kernel(const void* __restrict__ ei, int e) {
    int i = blockIdx.x * blockDim.x + threadIdx.x;
    if (i < e) {
        int d = load_idx(ei, (long long)e + i);  // dst row of edge_index
        atomicAdd(&g_deg[d], 1);
    }
}

// Single-block exclusive prefix sum over (deg[i]-1) -> rowptr; also dis[].
__global__ void scan_kernel(int n, int e_total) {
    __shared__ int sh[1024];
    int t = threadIdx.x;
    int ch = (n + 1023) / 1024;
    int beg = t * ch;
    int end = min(beg + ch, n);
    int s = 0;
    for (int i = beg; i < end; ++i) {
        int dg = g_deg[i];
        s += dg - 1;
        g_dis[i] = rsqrtf((float)dg);
    }
    sh[t] = s;
    __syncthreads();
    for (int off = 1; off < 1024; off <<= 1) {
        int v = sh[t];
        int u = (t >= off) ? sh[t - off] : 0;
        __syncthreads();
        sh[t] = v + u;
        __syncthreads();
    }
    int excl = (t == 0) ? 0 : sh[t - 1];
    for (int i = beg; i < end; ++i) {
        g_rowptr[i] = excl;
        excl += g_deg[i] - 1;
    }
    if (t == 1023) g_rowptr[n] = e_total;
}

// CSR fill: column indices only (one scattered 4B write per edge).
__global__ void fill_kernel(const void* __restrict__ ei, int e) {
    int i = blockIdx.x * blockDim.x + threadIdx.x;
    if (i >= e) return;
    int s = load_idx(ei, i);
    int d = load_idx(ei, (long long)e + i);
    int pos = g_rowptr[d] + atomicAdd(&g_fill[d], 1);
    g_col[pos] = s;
}

// ---------------- dense 64x64 GEMM, dis-scaled epilogue, fp16 output -------
// T[row] = half( dis[row] * (in[row] @ W) ).
__global__ void gemm64_kernel(const float* __restrict__ in,
                              const float* __restrict__ W,
                              __half2* __restrict__ outT, int n) {
    __shared__ float Ws[64 * 64];
    int tid = threadIdx.x;  // 256
#pragma unroll
    for (int i = 0; i < 16; ++i) Ws[tid + 256 * i] = W[tid + 256 * i];
    __syncthreads();

    int row  = blockIdx.x * 128 + (tid & 127);
    int half = tid >> 7;   // uniform per warp
    if (row >= n) return;

    float acc[32];
#pragma unroll
    for (int j = 0; j < 32; ++j) acc[j] = 0.f;

    const float4* xr = reinterpret_cast<const float4*>(in + row * 64);
    const float*  wb = Ws + half * 32;

#pragma unroll 2
    for (int k4 = 0; k4 < 16; ++k4) {
        float4 xv = xr[k4];
        float xk[4] = {xv.x, xv.y, xv.z, xv.w};
#pragma unroll
        for (int kk = 0; kk < 4; ++kk) {
            const float4* wrow =
                reinterpret_cast<const float4*>(wb + (k4 * 4 + kk) * 64);
#pragma unroll
            for (int j4 = 0; j4 < 8; ++j4) {
                float4 wv = wrow[j4];
                acc[j4 * 4 + 0] += xk[kk] * wv.x;
                acc[j4 * 4 + 1] += xk[kk] * wv.y;
                acc[j4 * 4 + 2] += xk[kk] * wv.z;
                acc[j4 * 4 + 3] += xk[kk] * wv.w;
            }
        }
    }

    float ds = g_dis[row];
    __half2 hh[16];
#pragma unroll
    for (int j2 = 0; j2 < 16; ++j2)
        hh[j2] = __floats2half2_rn(ds * acc[j2 * 2], ds * acc[j2 * 2 + 1]);

    uint4* o = reinterpret_cast<uint4*>(outT + row * 32 + half * 16);
    const uint4* hsrc = reinterpret_cast<const uint4*>(hh);
#pragma unroll
    for (int j = 0; j < 4; ++j) o[j] = hsrc[j];
}

// ---------------- aggregation: 2 nodes per warp (2 independent chains) -----
// Half-warp per node: 16 lanes x 8B (uint2 = 2 half2 = 4 features) covers the
// 128B fp16 row. Two independent edge streams per warp double memory-level
// parallelism without front-batched load bursts.
__global__ void agg_kernel(const __half2* __restrict__ t,
                           const float* __restrict__ bias,
                           float* __restrict__ outH, int n) {
    int warp = (blockIdx.x * blockDim.x + threadIdx.x) >> 5;
    int lane = threadIdx.x & 31;
    int sub  = lane >> 4;          // 0 or 1: which node of the pair
    int fl   = lane & 15;          // feature lane: owns features 4*fl..4*fl+3
    int node = warp * 2 + sub;
    if (node >= n) return;

    const uint2* tu = reinterpret_cast<const uint2*>(t);

    // self-loop term
    uint2 raw = tu[node * 16 + fl];
    __half2 h0 = *reinterpret_cast<__half2*>(&raw.x);
    __half2 h1 = *reinterpret_cast<__half2*>(&raw.y);
    float2 a0 = __half22float2(h0);
    float2 a1 = __half22float2(h1);

    int beg = g_rowptr[node];
    int end = g_rowptr[node + 1];
    for (int e = beg; e < end; ++e) {
        int s = g_col[e];
        uint2 r = tu[s * 16 + fl];
        __half2 v0 = *reinterpret_cast<__half2*>(&r.x);
        __half2 v1 = *reinterpret_cast<__half2*>(&r.y);
        float2 f0 = __half22float2(v0);
        float2 f1 = __half22float2(v1);
        a0.x += f0.x; a0.y += f0.y;
        a1.x += f1.x; a1.y += f1.y;
    }

    float d = g_dis[node];
    float4 b = *reinterpret_cast<const float4*>(bias + fl * 4);
    float4 r;
    r.x = fmaxf(d * a0.x + b.x, 0.f);
    r.y = fmaxf(d * a0.y + b.y, 0.f);
    r.z = fmaxf(d * a1.x + b.z, 0.f);
    r.w = fmaxf(d * a1.y + b.w, 0.f);
    *reinterpret_cast<float4*>(outH + node * 64 + fl * 4) = r;
}

// ---------------- mean pool + MLP + log_softmax (block per graph) ---------
__device__ __forceinline__ int lower_bound_batch(const void* batch, int n, int key) {
    int lo = 0, hi = n;
    while (lo < hi) {
        int mid = (lo + hi) >> 1;
        if (load_idx(batch, mid) < key) lo = mid + 1;
        else hi = mid;
    }
    return lo;
}

__global__ void pool_mlp_kernel(const float* __restrict__ h,
                                const void* __restrict__ batch, int n,
                                const float* __restrict__ lin1W,
                                const float* __restrict__ lin1b,
                                const float* __restrict__ lin2W,
                                const float* __restrict__ lin2b,
                                float* __restrict__ out) {
    int g   = blockIdx.x;
    int tid = threadIdx.x;  // 64
    __shared__ float pooled[64];
    __shared__ float h1[64];
    __shared__ float logits[10];
    __shared__ float lse;
    __shared__ int   sbeg, send;

    if (tid == 0) sbeg = lower_bound_batch(batch, n, g);
    if (tid == 32) send = lower_bound_batch(batch, n, g + 1);
    __syncthreads();
    int beg = sbeg, end = send;

    float s = 0.f;
    for (int r = beg; r < end; ++r) s += h[r * 64 + tid];
    int cnt = end - beg;
    pooled[tid] = s / (float)max(cnt, 1);
    __syncthreads();

    float a = lin1b[tid];
#pragma unroll
    for (int k = 0; k < 64; ++k) a += pooled[k] * lin1W[k * 64 + tid];
    h1[tid] = fmaxf(a, 0.f);
    __syncthreads();

    if (tid < 10) {
        float l = lin2b[tid];
#pragma unroll
        for (int k = 0; k < 64; ++k) l += h1[k] * lin2W[k * 10 + tid];
        logits[tid] = l;
    }
    __syncthreads();

    if (tid == 0) {
        float m = logits[0];
        for (int j = 1; j < 10; ++j) m = fmaxf(m, logits[j]);
        float se = 0.f;
        for (int j = 0; j < 10; ++j) se += expf(logits[j] - m);
        lse = m + logf(se);
    }
    __syncthreads();

    if (tid < 10) out[g * 10 + tid] = logits[tid] - lse;
}

// ---------------- launch ---------------------------------------------------
extern "C" void kernel_launch(void* const* d_in, const int* in_sizes, int n_in,
                              void* d_out, int out_size) {
    const float* x     = (const float*)d_in[0];
    const void*  ei    = d_in[1];
    const void*  batch = d_in[2];
    const float* W1 = (const float*)d_in[3];
    const float* b1 = (const float*)d_in[4];
    const float* W2 = (const float*)d_in[5];
    const float* b2 = (const float*)d_in[6];
    const float* W3 = (const float*)d_in[7];
    const float* b3 = (const float*)d_in[8];
    const float* l1W = (const float*)d_in[9];
    const float* l1b = (const float*)d_in[10];
    const float* l2W = (const float*)d_in[11];
    const float* l2b = (const float*)d_in[12];
    float* out = (float*)d_out;

    const int n = in_sizes[0] / HID;
    const int e = in_sizes[1] / 2;
    const int G = out_size / 10;

    __half2* bufT = nullptr;
    float*   bufH = nullptr;
    cudaGetSymbolAddress((void**)&bufT, g_bufT);
    cudaGetSymbolAddress((void**)&bufH, g_bufH);

    cudaStream_t s2;
    cudaEvent_t evFork, evJoin;
    cudaStreamCreateWithFlags(&s2, cudaStreamNonBlocking);
    cudaEventCreateWithFlags(&evFork, cudaEventDisableTiming);
    cudaEventCreateWithFlags(&evJoin, cudaEventDisableTiming);

    int tpb = 256;
    detect_init_kernel<<<(n + tpb - 1) / tpb, tpb>>>((const int*)ei, n);
    deg_kernel<<<(e + tpb - 1) / tpb, tpb>>>(ei, e);
    scan_kernel<<<1, 1024>>>(n, e);

    // fork: fill (CSR columns) concurrently with gemm1
    cudaEventRecord(evFork, 0);
    cudaStreamWaitEvent(s2, evFork, 0);
    fill_kernel<<<(e + tpb - 1) / tpb, tpb, 0, s2>>>(ei, e);
    cudaEventRecord(evJoin, s2);

    int gemm_blocks = (n + 127) / 128;
    int npairs      = (n + 1) / 2;
    int agg_blocks  = (npairs * 32 + tpb - 1) / tpb;

    gemm64_kernel<<<gemm_blocks, 256>>>(x, W1, bufT, n);   // T1

    cudaStreamWaitEvent(0, evJoin, 0);  // aggs need the CSR columns

    agg_kernel<<<agg_blocks, tpb>>>(bufT, b1, bufH, n);    // H1
    gemm64_kernel<<<gemm_blocks, 256>>>(bufH, W2, bufT, n); // T2
    agg_kernel<<<agg_blocks, tpb>>>(bufT, b2, bufH, n);    // H2
    gemm64_kernel<<<gemm_blocks, 256>>>(bufH, W3, bufT, n); // T3
    agg_kernel<<<agg_blocks, tpb>>>(bufT, b3, bufH, n);    // H3

    pool_mlp_kernel<<<G, 64>>>(bufH, batch, n, l1W, l1b, l2W, l2b, out);
}